// round 16
// baseline (speedup 1.0000x reference)
#include <cuda_runtime.h>

#define POOL   7
#define NPIX   49
#define BATCH  2
#define NBOX   1000
#define CCH    256
#define C4     (CCH / 4)
#define ITEMS  (NPIX * C4)      // 3136 float4 items per box
#define NUNITS (BATCH * NBOX * 2)
#define GRID   1184             // 148 SMs x 8 blocks

// ---------------------------------------------------------------------------
// Persistent fused kernel: 1184 resident blocks, each loops over (box, half)
// units. Per unit: slot rank scan + pixel params + streamed bilinear.
// ---------------------------------------------------------------------------
__global__ __launch_bounds__(256, 8) void roi_kernel(
    const float* __restrict__ boxes,
    const float* __restrict__ fm0,
    const float* __restrict__ fm1,
    const float* __restrict__ fm2,
    const float* __restrict__ fm3,
    const int*   __restrict__ level,
    float*       __restrict__ out)
{
    __shared__ int4   sIdx[NPIX];   // corner base indices (float4 units)
    __shared__ float4 sW[NPIX];     // {w_tl, w_tr, w_bl, w_br} (valid folded)
    __shared__ int    sRed[8];
    __shared__ int    sSlot;

    const int tid  = threadIdx.x;
    const int warp = tid >> 5, lane = tid & 31;

    for (int blk = blockIdx.x; blk < NUNITS; blk += GRID) {
        const int box  = blk >> 1;                // 0..1999
        const int half = blk & 1;                 // channel half
        const int b    = (box >= NBOX) ? 1 : 0;
        const int ii   = box - b * NBOX;          // index within batch

        const int myLv = __ldg(level + box);      // 1..4

        const float* fm; int S;
        switch (myLv - 1) {
            case 0:  fm = fm0; S = 256; break;
            case 1:  fm = fm1; S = 128; break;
            case 2:  fm = fm2; S = 64;  break;
            default: fm = fm3; S = 32;  break;
        }

        // ---- slot: predicate count over this batch's 1000 levels ----
        {
            const int* lvArr = level + b * NBOX;
            int cnt = 0;
            #pragma unroll
            for (int j = tid; j < NBOX; j += 256) {
                const int lj = __ldg(lvArr + j);
                cnt += (lj < myLv) || (lj == myLv && j < ii);
            }
            #pragma unroll
            for (int d = 16; d; d >>= 1) cnt += __shfl_xor_sync(0xffffffffu, cnt, d);
            if (lane == 0) sRed[warp] = cnt;
        }

        // ---- per-pixel params (threads 0..48) ----
        if (tid < NPIX) {
            const int py = tid / POOL;
            const int px = tid - py * POOL;
            const float sm1 = (float)(S - 1);

            const float y1 = __ldg(boxes + box * 4 + 0);
            const float x1 = __ldg(boxes + box * 4 + 1);
            const float y2 = __ldg(boxes + box * 4 + 2);
            const float x2 = __ldg(boxes + box * 4 + 3);

            const float in_y = y1 * sm1 + (float)py * ((y2 - y1) * sm1 / 6.0f);
            const float in_x = x1 * sm1 + (float)px * ((x2 - x1) * sm1 / 6.0f);

            const bool valid = (in_y >= 0.0f) && (in_y <= sm1) &&
                               (in_x >= 0.0f) && (in_x <= sm1);
            const float v = valid ? 1.0f : 0.0f;

            const float fy = floorf(in_y);
            const float fx = floorf(in_x);
            const int ty = (int)fminf(fmaxf(fy, 0.0f), sm1);
            const int by = min(ty + 1, S - 1);
            const int lx = (int)fminf(fmaxf(fx, 0.0f), sm1);
            const int rx = min(lx + 1, S - 1);

            const float wy = in_y - fy, wx = in_x - fx;
            const float oy = 1.0f - wy, ox = 1.0f - wx;

            const int rowT = (b * S + ty) * S;
            const int rowB = (b * S + by) * S;
            sIdx[tid] = make_int4((rowT + lx) * C4, (rowT + rx) * C4,
                                  (rowB + lx) * C4, (rowB + rx) * C4);
            sW[tid] = make_float4(oy * ox * v, oy * wx * v,
                                  wy * ox * v, wy * wx * v);
        }
        __syncthreads();
        if (tid == 0) {
            int s = 0;
            #pragma unroll
            for (int w = 0; w < 8; ++w) s += sRed[w];
            sSlot = s;
        }
        __syncthreads();

        const float4* f4 = (const float4*)fm;
        float4* o4 = (float4*)out + (size_t)(b * NBOX + sSlot) * ITEMS;

        const int c    = (tid & 31) + (half << 5);  // channel group 0..63
        const int slot = tid >> 5;                  // 0..7 (== warp id)

        #pragma unroll
        for (int k = 0; k < 6; ++k) {
            const int pix = k * 8 + slot;           // 0..47

            const int4   id = sIdx[pix];
            const float4 w  = sW[pix];              // corner weights

            const float4 tl = __ldg(f4 + id.x + c);
            const float4 tr = __ldg(f4 + id.y + c);
            const float4 bl = __ldg(f4 + id.z + c);
            const float4 br = __ldg(f4 + id.w + c);

            float4 r;
            r.x = tl.x * w.x + tr.x * w.y + bl.x * w.z + br.x * w.w;
            r.y = tl.y * w.x + tr.y * w.y + bl.y * w.z + br.y * w.w;
            r.z = tl.z * w.x + tr.z * w.y + bl.z * w.z + br.z * w.w;
            r.w = tl.w * w.x + tr.w * w.y + bl.w * w.z + br.w * w.w;
            __stcs(o4 + pix * C4 + c, r);
        }

        // tail: pixel 48 (warp 0 only)
        if (slot == 0) {
            const int4   id = sIdx[48];
            const float4 w  = sW[48];
            const float4 tl = __ldg(f4 + id.x + c);
            const float4 tr = __ldg(f4 + id.y + c);
            const float4 bl = __ldg(f4 + id.z + c);
            const float4 br = __ldg(f4 + id.w + c);
            float4 r;
            r.x = tl.x * w.x + tr.x * w.y + bl.x * w.z + br.x * w.w;
            r.y = tl.y * w.x + tr.y * w.y + bl.y * w.z + br.y * w.w;
            r.z = tl.z * w.x + tr.z * w.y + bl.z * w.z + br.z * w.w;
            r.w = tl.w * w.x + tr.w * w.y + bl.w * w.z + br.w * w.w;
            __stcs(o4 + 48 * C4 + c, r);
        }

        __syncthreads();   // shared arrays reused by next unit
    }
}

// ---------------------------------------------------------------------------
// Launch: single persistent kernel, one wave.
// ---------------------------------------------------------------------------
extern "C" void kernel_launch(void* const* d_in, const int* in_sizes, int n_in,
                              void* d_out, int out_size) {
    const float* boxes = (const float*)d_in[0];
    const float* fm0   = (const float*)d_in[1];
    const float* fm1   = (const float*)d_in[2];
    const float* fm2   = (const float*)d_in[3];
    const float* fm3   = (const float*)d_in[4];
    const int*   level = (const int*)  d_in[5];
    float*       out   = (float*)d_out;

    roi_kernel<<<GRID, 256>>>(boxes, fm0, fm1, fm2, fm3, level, out);
}

// round 17
// speedup vs baseline: 1.1408x; 1.1408x over previous
#include <cuda_runtime.h>

#define POOL   7
#define NPIX   49
#define BATCH  2
#define NBOX   1000
#define CCH    256
#define C4     (CCH / 4)
#define ITEMS  (NPIX * C4)      // 3136 float4 items per box

// ---------------------------------------------------------------------------
// Fused kernel: one block per (box, channel-half). 4000 blocks x 256 threads.
//  - slot rank scan: one LDG.128 per thread (250 int4 cover 1000 levels),
//    single __syncthreads, every thread sums the 8 warp partials itself.
//  - per-pixel params: corner indices + 4 scalar corner weights (valid folded)
//  - hot loop: 4x LDG.128 + 2x LDS.128 + 16 FMA + 1 STG.128 per float4 item.
// ---------------------------------------------------------------------------
__global__ __launch_bounds__(256, 8) void roi_kernel(
    const float* __restrict__ boxes,
    const float* __restrict__ fm0,
    const float* __restrict__ fm1,
    const float* __restrict__ fm2,
    const float* __restrict__ fm3,
    const int*   __restrict__ level,
    float*       __restrict__ out)
{
    __shared__ int4   sIdx[NPIX];   // corner base indices (float4 units)
    __shared__ float4 sW[NPIX];     // {w_tl, w_tr, w_bl, w_br} (valid folded)
    __shared__ int    sRed[8];

    const int blk  = blockIdx.x;              // 0..3999
    const int box  = blk >> 1;                // 0..1999
    const int half = blk & 1;                 // channel half
    const int b    = (box >= NBOX) ? 1 : 0;
    const int ii   = box - b * NBOX;          // index within batch
    const int tid  = threadIdx.x;
    const int warp = tid >> 5, lane = tid & 31;

    const int myLv = __ldg(level + box);      // 1..4

    const float* fm; int S;
    switch (myLv - 1) {
        case 0:  fm = fm0; S = 256; break;
        case 1:  fm = fm1; S = 128; break;
        case 2:  fm = fm2; S = 64;  break;
        default: fm = fm3; S = 32;  break;
    }

    // ---- slot: predicate count over this batch's 1000 levels ----
    // 250 int4 granules cover levels [0,1000). Thread t (t<250) handles
    // indices 4t..4t+3.
    {
        const int4* lvArr = (const int4*)(level + b * NBOX);
        int cnt = 0;
        if (tid < 250) {
            const int4 lj = __ldg(lvArr + tid);
            const int j0 = tid * 4;
            cnt += (lj.x < myLv) || (lj.x == myLv && j0     < ii);
            cnt += (lj.y < myLv) || (lj.y == myLv && j0 + 1 < ii);
            cnt += (lj.z < myLv) || (lj.z == myLv && j0 + 2 < ii);
            cnt += (lj.w < myLv) || (lj.w == myLv && j0 + 3 < ii);
        }
        #pragma unroll
        for (int d = 16; d; d >>= 1) cnt += __shfl_xor_sync(0xffffffffu, cnt, d);
        if (lane == 0) sRed[warp] = cnt;
    }

    // ---- per-pixel params (threads 0..48) ----
    if (tid < NPIX) {
        const int py = tid / POOL;
        const int px = tid - py * POOL;
        const float sm1 = (float)(S - 1);

        const float y1 = __ldg(boxes + box * 4 + 0);
        const float x1 = __ldg(boxes + box * 4 + 1);
        const float y2 = __ldg(boxes + box * 4 + 2);
        const float x2 = __ldg(boxes + box * 4 + 3);

        const float in_y = y1 * sm1 + (float)py * ((y2 - y1) * sm1 / 6.0f);
        const float in_x = x1 * sm1 + (float)px * ((x2 - x1) * sm1 / 6.0f);

        const bool valid = (in_y >= 0.0f) && (in_y <= sm1) &&
                           (in_x >= 0.0f) && (in_x <= sm1);
        const float v = valid ? 1.0f : 0.0f;

        const float fy = floorf(in_y);
        const float fx = floorf(in_x);
        const int ty = (int)fminf(fmaxf(fy, 0.0f), sm1);
        const int by = min(ty + 1, S - 1);
        const int lx = (int)fminf(fmaxf(fx, 0.0f), sm1);
        const int rx = min(lx + 1, S - 1);

        const float wy = in_y - fy, wx = in_x - fx;
        const float oy = 1.0f - wy, ox = 1.0f - wx;

        const int rowT = (b * S + ty) * S;
        const int rowB = (b * S + by) * S;
        sIdx[tid] = make_int4((rowT + lx) * C4, (rowT + rx) * C4,
                              (rowB + lx) * C4, (rowB + rx) * C4);
        sW[tid] = make_float4(oy * ox * v, oy * wx * v,
                              wy * ox * v, wy * wx * v);
    }
    __syncthreads();

    // every thread sums the 8 warp partials (broadcast LDS, no extra sync)
    int slotRank = 0;
    #pragma unroll
    for (int w = 0; w < 8; ++w) slotRank += sRed[w];

    const float4* f4 = (const float4*)fm;
    float4* o4 = (float4*)out + (size_t)(b * NBOX + slotRank) * ITEMS;

    const int c    = (tid & 31) + (half << 5);  // channel group 0..63
    const int slot = tid >> 5;                  // 0..7 (== warp id)

    #pragma unroll
    for (int k = 0; k < 6; ++k) {
        const int pix = k * 8 + slot;           // 0..47

        const int4   id = sIdx[pix];
        const float4 w  = sW[pix];              // corner weights

        const float4 tl = __ldg(f4 + id.x + c);
        const float4 tr = __ldg(f4 + id.y + c);
        const float4 bl = __ldg(f4 + id.z + c);
        const float4 br = __ldg(f4 + id.w + c);

        float4 r;
        r.x = tl.x * w.x + tr.x * w.y + bl.x * w.z + br.x * w.w;
        r.y = tl.y * w.x + tr.y * w.y + bl.y * w.z + br.y * w.w;
        r.z = tl.z * w.x + tr.z * w.y + bl.z * w.z + br.z * w.w;
        r.w = tl.w * w.x + tr.w * w.y + bl.w * w.z + br.w * w.w;
        __stcs(o4 + pix * C4 + c, r);
    }

    // tail: pixel 48 (warp 0 only)
    if (slot == 0) {
        const int4   id = sIdx[48];
        const float4 w  = sW[48];
        const float4 tl = __ldg(f4 + id.x + c);
        const float4 tr = __ldg(f4 + id.y + c);
        const float4 bl = __ldg(f4 + id.z + c);
        const float4 br = __ldg(f4 + id.w + c);
        float4 r;
        r.x = tl.x * w.x + tr.x * w.y + bl.x * w.z + br.x * w.w;
        r.y = tl.y * w.x + tr.y * w.y + bl.y * w.z + br.y * w.w;
        r.z = tl.z * w.x + tr.z * w.y + bl.z * w.z + br.z * w.w;
        r.w = tl.w * w.x + tr.w * w.y + bl.w * w.z + br.w * w.w;
        __stcs(o4 + 48 * C4 + c, r);
    }
}

// ---------------------------------------------------------------------------
// Launch: single fused kernel.
// ---------------------------------------------------------------------------
extern "C" void kernel_launch(void* const* d_in, const int* in_sizes, int n_in,
                              void* d_out, int out_size) {
    const float* boxes = (const float*)d_in[0];
    const float* fm0   = (const float*)d_in[1];
    const float* fm1   = (const float*)d_in[2];
    const float* fm2   = (const float*)d_in[3];
    const float* fm3   = (const float*)d_in[4];
    const int*   level = (const int*)  d_in[5];
    float*       out   = (float*)d_out;

    roi_kernel<<<BATCH * NBOX * 2, 256>>>(boxes, fm0, fm1, fm2, fm3, level, out);
}